// round 1
// baseline (speedup 1.0000x reference)
#include <cuda_runtime.h>
#include <cuda_bf16.h>
#include <math.h>

// Problem constants
#define B_  2
#define N_  2048
#define D_  1024
#define H_  16
#define DH_ 64
#define ROWS_ (B_*N_)          // 4096
#define BHN_  (B_*H_*N_)       // 65536

// Scratch (static device globals — no allocation)
__device__ float g_q[B_*H_*N_*DH_];
__device__ float g_k[B_*H_*N_*DH_];
__device__ float g_v[B_*H_*N_*DH_];
__device__ float g_ctx[B_*N_*D_];
__device__ float g_qn[BHN_];
__device__ float g_kn[BHN_];

__device__ __forceinline__ float softplusf(float x) {
    return (x > 20.f) ? x : log1pf(__expf(x));
}

// ---------------------------------------------------------------------------
// SGEMM: out = A[4096,1024] @ W[1024,1024]^T
// BM=BN=128, BK=16, 256 threads, 8x8 microtile.
// blockIdx.z selects (W, C) among the three passed pointer sets.
// headLayout: write C[((b*16+h)*2048+n)*64+dh] instead of row-major.
// ---------------------------------------------------------------------------
__global__ __launch_bounds__(256, 2)
void sgemm_xwt(const float* __restrict__ A,
               const float* __restrict__ W0, const float* __restrict__ W1,
               const float* __restrict__ W2,
               float* __restrict__ C0, float* __restrict__ C1,
               float* __restrict__ C2,
               int headLayout)
{
    const int K = D_;
    const float* __restrict__ W = (blockIdx.z == 0) ? W0 : (blockIdx.z == 1) ? W1 : W2;
    float* __restrict__ C       = (blockIdx.z == 0) ? C0 : (blockIdx.z == 1) ? C1 : C2;

    __shared__ float As[16][128];
    __shared__ float Bs[16][128];

    const int tid = threadIdx.x;
    const int tx = tid & 15;          // 0..15 -> N
    const int ty = tid >> 4;          // 0..15 -> M
    const int rowBase = blockIdx.y * 128;
    const int colBase = blockIdx.x * 128;

    float acc[8][8];
#pragma unroll
    for (int u = 0; u < 8; u++)
#pragma unroll
        for (int v = 0; v < 8; v++) acc[u][v] = 0.f;

    for (int kk = 0; kk < K; kk += 16) {
#pragma unroll
        for (int i = 0; i < 2; i++) {
            int f  = tid + i * 256;        // 0..511
            int r  = f >> 2;               // 0..127
            int kq = (f & 3) * 4;          // 0,4,8,12
            float4 a = *(const float4*)(A + (size_t)(rowBase + r) * K + kk + kq);
            As[kq + 0][r] = a.x; As[kq + 1][r] = a.y;
            As[kq + 2][r] = a.z; As[kq + 3][r] = a.w;
            float4 b = *(const float4*)(W + (size_t)(colBase + r) * K + kk + kq);
            Bs[kq + 0][r] = b.x; Bs[kq + 1][r] = b.y;
            Bs[kq + 2][r] = b.z; Bs[kq + 3][r] = b.w;
        }
        __syncthreads();
#pragma unroll
        for (int k = 0; k < 16; k++) {
            float af[8], bf[8];
            *(float4*)(af)     = *(const float4*)&As[k][ty * 8];
            *(float4*)(af + 4) = *(const float4*)&As[k][ty * 8 + 4];
            *(float4*)(bf)     = *(const float4*)&Bs[k][tx * 8];
            *(float4*)(bf + 4) = *(const float4*)&Bs[k][tx * 8 + 4];
#pragma unroll
            for (int u = 0; u < 8; u++)
#pragma unroll
                for (int v = 0; v < 8; v++)
                    acc[u][v] = fmaf(af[u], bf[v], acc[u][v]);
        }
        __syncthreads();
    }

    // Epilogue
#pragma unroll
    for (int u = 0; u < 8; u++) {
        int row = rowBase + ty * 8 + u;
#pragma unroll
        for (int vv = 0; vv < 2; vv++) {
            int col = colBase + tx * 8 + vv * 4;
            float4 val = make_float4(acc[u][vv*4+0], acc[u][vv*4+1],
                                     acc[u][vv*4+2], acc[u][vv*4+3]);
            if (headLayout) {
                int b = row >> 11, n = row & 2047;
                int h = col >> 6,  dh = col & 63;
                *(float4*)(C + (((size_t)(b * H_ + h)) * N_ + n) * DH_ + dh) = val;
            } else {
                *(float4*)(C + (size_t)row * D_ + col) = val;
            }
        }
    }
}

// ---------------------------------------------------------------------------
// Row squared-norms: one warp per 64-elem row of g_q / g_k.
// ---------------------------------------------------------------------------
__global__ void row_norms(const float* __restrict__ q, const float* __restrict__ k,
                          float* __restrict__ qn, float* __restrict__ kn)
{
    int gw = (blockIdx.x * blockDim.x + threadIdx.x) >> 5;  // global warp = row
    int lane = threadIdx.x & 31;
    if (gw >= BHN_) return;
    const float* src = (blockIdx.y == 0) ? q : k;
    float*       dst = (blockIdx.y == 0) ? qn : kn;
    const float* r = src + (size_t)gw * DH_;
    float a = r[lane], b = r[lane + 32];
    float s = a * a + b * b;
#pragma unroll
    for (int off = 16; off > 0; off >>= 1)
        s += __shfl_xor_sync(0xFFFFFFFFu, s, off);
    if (lane == 0) dst[gw] = s;
}

// ---------------------------------------------------------------------------
// Hyperbolic flash attention, fp32.
// grid = (N/64, B*H), block = 64 threads. Thread t owns row r0+t.
// ---------------------------------------------------------------------------
__global__ __launch_bounds__(64)
void hyp_attn(const float* __restrict__ qp, const float* __restrict__ kp,
              const float* __restrict__ vp,
              const float* __restrict__ qnp, const float* __restrict__ knp,
              float* __restrict__ ctx,
              const float* __restrict__ logc_p, const float* __restrict__ logb_p)
{
    __shared__ float ks[64 * 64];
    __shared__ float vs[64 * 64];
    __shared__ float ps[64 * 65];
    __shared__ float kns[64];

    const int tid = threadIdx.x;
    const int bh  = blockIdx.y;
    const int r0  = blockIdx.x * 64;
    const int row = r0 + tid;

    const float c    = softplusf(*logc_p);
    const float beta = softplusf(*logb_p) + 0.5f;

    // Stage Q block through smem (coalesced), then into registers.
    {
        const float* qblk = qp + ((size_t)bh * N_ + r0) * DH_;
#pragma unroll
        for (int i = 0; i < 64; i++)
            ps[i * 65 + tid] = qblk[(size_t)i * DH_ + tid];
    }
    __syncthreads();
    float q[DH_];
#pragma unroll
    for (int d = 0; d < DH_; d++) q[d] = ps[tid * 65 + d];
    const float qn = qnp[bh * N_ + row];

    float mprev = -1e30f, l = 0.f;
    float o[DH_];
#pragma unroll
    for (int d = 0; d < DH_; d++) o[d] = 0.f;

    const int ntiles = blockIdx.x + 1;
    for (int T = 0; T < ntiles; T++) {
        const int t0 = T * 64;
        __syncthreads();   // protect ks/vs from prior-iteration readers
        {
            const float4* kblk = (const float4*)(kp + ((size_t)bh * N_ + t0) * DH_);
            const float4* vblk = (const float4*)(vp + ((size_t)bh * N_ + t0) * DH_);
            float4* k4 = (float4*)ks;
            float4* v4 = (float4*)vs;
#pragma unroll
            for (int i = 0; i < 16; i++) {
                int f = i * 64 + tid;
                k4[f] = kblk[f];
                v4[f] = vblk[f];
            }
            kns[tid] = knp[bh * N_ + t0 + tid];
        }
        __syncthreads();

        const bool diag = (T == blockIdx.x);
        float tmax = -1e30f;
        for (int m = 0; m < 64; m++) {
            float s0 = 0.f, s1 = 0.f, s2 = 0.f, s3 = 0.f;
            const float* krow = &ks[m * 64];
#pragma unroll
            for (int d = 0; d < 64; d += 4) {
                s0 = fmaf(q[d + 0], krow[d + 0], s0);
                s1 = fmaf(q[d + 1], krow[d + 1], s1);
                s2 = fmaf(q[d + 2], krow[d + 2], s2);
                s3 = fmaf(q[d + 3], krow[d + 3], s3);
            }
            float s = (s0 + s1) + (s2 + s3);
            float kn = kns[m];
            float diff = fmaxf(qn - 2.f * s + kn, 0.f);
            float ed = sqrtf(diff + 1e-8f);
            float ns = qn + kn;
            float cns = c * ns;
            float dist;
            if (ed < 0.1f)
                dist = ed * (1.f + 0.5f * cns + 0.125f * cns * cns);
            else if (ed > 2.0f)
                dist = 0.693f + __logf(ed + 1e-8f) + 0.25f * cns;
            else
                dist = ed * sqrtf(1.f + cns);
            float sc = -beta * dist;
            if (diag && (t0 + m > row)) sc = -1e30f;
            ps[tid * 65 + m] = sc;
            tmax = fmaxf(tmax, sc);
        }

        float mnew = fmaxf(mprev, tmax);
        float corr = __expf(mprev - mnew);
        l *= corr;
#pragma unroll
        for (int d = 0; d < DH_; d++) o[d] *= corr;

        for (int m = 0; m < 64; m++) {
            float p = __expf(ps[tid * 65 + m] - mnew);
            l += p;
            const float* vrow = &vs[m * 64];
#pragma unroll
            for (int d = 0; d < DH_; d++)
                o[d] = fmaf(p, vrow[d], o[d]);
        }
        mprev = mnew;
    }

    // Write ctx[(b*N + row)*D + h*64 + d]
    const float inv = 1.f / l;
    const int b = bh >> 4, h = bh & 15;
    float* outp = ctx + ((size_t)b * N_ + row) * D_ + h * DH_;
#pragma unroll
    for (int d4 = 0; d4 < 16; d4++) {
        float4 val = make_float4(o[d4*4+0]*inv, o[d4*4+1]*inv,
                                 o[d4*4+2]*inv, o[d4*4+3]*inv);
        *(float4*)(outp + d4 * 4) = val;
    }
}

// ---------------------------------------------------------------------------
extern "C" void kernel_launch(void* const* d_in, const int* in_sizes, int n_in,
                              void* d_out, int out_size)
{
    const float* x     = (const float*)d_in[0];
    const float* Wq    = (const float*)d_in[1];
    const float* Wk    = (const float*)d_in[2];
    const float* Wv    = (const float*)d_in[3];
    const float* Wo    = (const float*)d_in[4];
    const float* log_c = (const float*)d_in[5];
    const float* log_b = (const float*)d_in[6];
    float* out = (float*)d_out;

    float *qptr, *kptr, *vptr, *ctxptr, *qnp, *knp;
    cudaGetSymbolAddress((void**)&qptr,  g_q);
    cudaGetSymbolAddress((void**)&kptr,  g_k);
    cudaGetSymbolAddress((void**)&vptr,  g_v);
    cudaGetSymbolAddress((void**)&ctxptr, g_ctx);
    cudaGetSymbolAddress((void**)&qnp,   g_qn);
    cudaGetSymbolAddress((void**)&knp,   g_kn);

    // QKV projections (fused into one launch via z)
    dim3 gq(D_ / 128, ROWS_ / 128, 3);   // (8, 32, 3)
    sgemm_xwt<<<gq, 256>>>(x, Wq, Wk, Wv, qptr, kptr, vptr, 1);

    // Row norms
    dim3 gn((BHN_ / 8 + 31) / 32 * 32 / 32, 2);  // warps: BHN_ rows, 8 warps/block
    row_norms<<<dim3(BHN_ / 8, 2), 256>>>(qptr, kptr, qnp, knp);

    // Attention
    hyp_attn<<<dim3(N_ / 64, B_ * H_), 64>>>(qptr, kptr, vptr, qnp, knp, ctxptr,
                                             log_c, log_b);

    // Output projection
    dim3 go(D_ / 128, ROWS_ / 128, 1);
    sgemm_xwt<<<go, 256>>>(ctxptr, Wo, Wo, Wo, out, out, out, 0);
}